// round 1
// baseline (speedup 1.0000x reference)
#include <cuda_runtime.h>
#include <math.h>

// Problem shape (fixed by the dataset): predictions/targets (N=32, C=1, H=1024, W=1024) f32.
#define HDIM 1024
#define WDIM 1024
#define TW   64            // columns per block
#define RSEG 4             // row segments per column
#define SEGROWS (HDIM / RSEG)      // 256
#define NTHREADS (TW * RSEG)       // 256
#define MAXBLOCKS 1024             // room for up to N=64 batches

// Per-block partial results (written unconditionally every launch -> deterministic, no zeroing needed)
__device__ float              g_blk_bce[MAXBLOCKS];
__device__ unsigned long long g_blk_pen[MAXBLOCKS];
__device__ unsigned int       g_blk_cnt[MAXBLOCKS];

__global__ __launch_bounds__(NTHREADS)
void dtl_main(const float* __restrict__ pred, const float* __restrict__ targ) {
    __shared__ unsigned int mask[HDIM / 32][TW];  // [word][col] target bitmask, 8KB

    const int tid = threadIdx.x;
    const int c   = tid & (TW - 1);
    const int r   = tid / TW;
    const int n   = blockIdx.y;
    const int w   = blockIdx.x * TW + c;

    const float* tcol = targ + ((size_t)n * HDIM) * WDIM + w;
    const float* pcol = pred + ((size_t)n * HDIM) * WDIM + w;

    const int i0 = r * SEGROWS;

    // ---- Phase 1: read targets, build per-column bitmask in SMEM ----
    #pragma unroll 2
    for (int k = 0; k < SEGROWS / 32; ++k) {      // 8 words per thread
        unsigned int m = 0;
        #pragma unroll
        for (int b = 0; b < 32; ++b) {
            float t = tcol[(size_t)(i0 + k * 32 + b) * WDIM];
            if (t == 1.0f) m |= (1u << b);
        }
        mask[r * 8 + k][c] = m;
    }
    __syncthreads();

    // ---- Phase 2: stream predictions, compute dist from bitmask ----
    // prev = largest target index <= current i (init: largest < i0)
    int prev = -(1 << 20);
    for (int wd = r * 8 - 1; wd >= 0; --wd) {
        unsigned int m = mask[wd][c];
        if (m) { prev = wd * 32 + 31 - __clz(m); break; }
    }
    // next = smallest target index >= current i
    int next = (1 << 20);
    for (int wd = r * 8; wd < HDIM / 32; ++wd) {
        unsigned int m = mask[wd][c];
        if (wd == r * 8) { /* full word, i0 is word-aligned */ }
        if (m) { next = wd * 32 + __ffs(m) - 1; break; }
    }

    float bce = 0.0f;
    unsigned int pen = 0, cnt = 0;

    #pragma unroll 4
    for (int i = i0; i < i0 + SEGROWS; ++i) {
        float p = pcol[(size_t)i * WDIM];

        bool is_t = false;
        if (i == next) {                 // i is a target
            is_t = true;
            prev = i;
            int s = i + 1;
            next = (1 << 20);
            int wd = s >> 5;
            if (wd < HDIM / 32) {
                unsigned int m = mask[wd][c] & (0xFFFFFFFFu << (s & 31));
                while (!m && ++wd < HDIM / 32) m = mask[wd][c];
                if (m) next = wd * 32 + __ffs(m) - 1;
            }
        }

        int dist = min(min(i - prev, next - i), HDIM);

        // BCE (stable form): max(p,0) - p*t + log1p(exp(-|p|))
        float ap = fabsf(p);
        float e  = __expf(-ap);
        bce += fmaxf(p, 0.0f) - (is_t ? p : 0.0f) + __logf(1.0f + e);

        if ((p > 0.0f) && (dist > 0)) { pen += (unsigned)dist; cnt++; }
    }

    // ---- Block reduction (deterministic tree) ----
    __shared__ float              s_bce[NTHREADS];
    __shared__ unsigned long long s_pen[NTHREADS];
    __shared__ unsigned int       s_cnt[NTHREADS];
    s_bce[tid] = bce; s_pen[tid] = pen; s_cnt[tid] = cnt;
    __syncthreads();
    for (int s = NTHREADS / 2; s > 0; s >>= 1) {
        if (tid < s) {
            s_bce[tid] += s_bce[tid + s];
            s_pen[tid] += s_pen[tid + s];
            s_cnt[tid] += s_cnt[tid + s];
        }
        __syncthreads();
    }
    if (tid == 0) {
        int b = blockIdx.y * gridDim.x + blockIdx.x;
        g_blk_bce[b] = s_bce[0];
        g_blk_pen[b] = s_pen[0];
        g_blk_cnt[b] = s_cnt[0];
    }
}

__global__ void dtl_final(float* __restrict__ out, int nblocks, double inv_count) {
    __shared__ double             sb[512];
    __shared__ unsigned long long sp[512];
    __shared__ unsigned long long sc[512];
    int t = threadIdx.x;
    double b = 0.0; unsigned long long p = 0, c = 0;
    for (int i = t; i < nblocks; i += 512) {
        b += (double)g_blk_bce[i];
        p += g_blk_pen[i];
        c += g_blk_cnt[i];
    }
    sb[t] = b; sp[t] = p; sc[t] = c;
    __syncthreads();
    for (int s = 256; s > 0; s >>= 1) {
        if (t < s) { sb[t] += sb[t + s]; sp[t] += sp[t + s]; sc[t] += sc[t + s]; }
        __syncthreads();
    }
    if (t == 0) {
        double bce_mean = sb[0] * inv_count;
        double total = (double)sp[0];
        unsigned long long cnt = sc[0] ? sc[0] : 1ull;
        double border = (total == 0.0) ? 0.0 : total / (double)cnt;
        out[0] = (float)(bce_mean + sqrt(border));
    }
}

extern "C" void kernel_launch(void* const* d_in, const int* in_sizes, int n_in,
                              void* d_out, int out_size) {
    const float* pred = (const float*)d_in[0];
    const float* targ = (const float*)d_in[1];
    const long long total = in_sizes[0];
    const int N = (int)(total / ((long long)HDIM * WDIM));   // 32

    dim3 grid(WDIM / TW, N);
    dtl_main<<<grid, NTHREADS>>>(pred, targ);

    const int nblocks = (WDIM / TW) * N;
    dtl_final<<<1, 512>>>((float*)d_out, nblocks, 1.0 / (double)total);
}

// round 2
// speedup vs baseline: 1.1055x; 1.1055x over previous
#include <cuda_runtime.h>
#include <math.h>

// Shape fixed by dataset: (N=32, C=1, H=1024, W=1024) f32.
#define HDIM 1024
#define WDIM 1024
#define W4   (WDIM / 4)        // 256 float4 per row
#define C4   32                // float4-columns per block (one warp-width)
#define CB   (C4 * 4)          // 128 scalar columns per block
#define RSEG 8                 // row segments
#define SEGROWS (HDIM / RSEG)  // 128 rows per thread
#define NWORDS (HDIM / 32)     // 32 mask words per column
#define WPT (SEGROWS / 32)     // 4 words built per thread
#define NTHREADS 256
#define MAXBLK 1024

// Cross-block accumulators. Zero-initialized at load; the last block resets
// them after use so every graph replay starts from the same state.
__device__ unsigned long long g_pen;
__device__ unsigned long long g_cnt;
__device__ float              g_bce[MAXBLK];
__device__ unsigned int       g_done;

__global__ __launch_bounds__(NTHREADS)
void dtl_main(const float* __restrict__ pred, const float* __restrict__ targ,
              float* __restrict__ out) {
    __shared__ unsigned int mask[NWORDS][CB + 4];   // [word][col], padded
    __shared__ float        s_bce[NTHREADS];
    __shared__ unsigned int s_pen[NTHREADS];
    __shared__ unsigned int s_cnt[NTHREADS];
    __shared__ bool         s_last;

    const int tid = threadIdx.x;
    const int c   = tid & 31;          // float4 lane within warp-row
    const int r   = tid >> 5;          // row segment 0..7
    const int n   = blockIdx.y;
    const int cb  = c * 4;             // scalar column base within block

    const float4* t4 = (const float4*)(targ + (size_t)n * HDIM * WDIM) + blockIdx.x * C4 + c;
    const float4* p4 = (const float4*)(pred + (size_t)n * HDIM * WDIM) + blockIdx.x * C4 + c;

    const int i0 = r * SEGROWS;

    // ---- Phase 1: stream targets (float4), build per-column bitmasks ----
    for (int k = 0; k < WPT; ++k) {
        unsigned m0 = 0, m1 = 0, m2 = 0, m3 = 0;
        #pragma unroll 8
        for (int b = 0; b < 32; ++b) {
            float4 t = __ldcs(&t4[(size_t)(i0 + k * 32 + b) * W4]);
            m0 |= (t.x == 1.0f ? 1u : 0u) << b;
            m1 |= (t.y == 1.0f ? 1u : 0u) << b;
            m2 |= (t.z == 1.0f ? 1u : 0u) << b;
            m3 |= (t.w == 1.0f ? 1u : 0u) << b;
        }
        const int wd = r * WPT + k;
        mask[wd][cb + 0] = m0;
        mask[wd][cb + 1] = m1;
        mask[wd][cb + 2] = m2;
        mask[wd][cb + 3] = m3;
    }
    __syncthreads();

    // ---- Phase 2: stream predictions, dist from bitmask, accumulate ----
    int prev[4], next[4];
    #pragma unroll
    for (int j = 0; j < 4; ++j) {
        prev[j] = -(1 << 20);
        for (int wd = r * WPT - 1; wd >= 0; --wd) {
            unsigned m = mask[wd][cb + j];
            if (m) { prev[j] = wd * 32 + 31 - __clz(m); break; }
        }
        next[j] = 1 << 20;
        for (int wd = r * WPT; wd < NWORDS; ++wd) {
            unsigned m = mask[wd][cb + j];
            if (m) { next[j] = wd * 32 + __ffs(m) - 1; break; }
        }
    }

    float bce = 0.0f;
    unsigned int pen = 0, cnt = 0;

    #pragma unroll 4
    for (int i = i0; i < i0 + SEGROWS; ++i) {
        float4 p = __ldcs(&p4[(size_t)i * W4]);
        float pv[4] = {p.x, p.y, p.z, p.w};
        #pragma unroll
        for (int j = 0; j < 4; ++j) {
            const bool is_t = (i == next[j]);
            if (is_t) {
                prev[j] = i;
                int s = i + 1;
                int wd = s >> 5;
                unsigned m = 0;
                if (wd < NWORDS) m = mask[wd][cb + j] & (0xFFFFFFFFu << (s & 31));
                while (!m && ++wd < NWORDS) m = mask[wd][cb + j];
                next[j] = m ? wd * 32 + __ffs(m) - 1 : (1 << 20);
            }
            const int dist = min(min(i - prev[j], next[j] - i), HDIM);
            const float v = pv[j];
            bce += fmaxf(v, 0.0f) - (is_t ? v : 0.0f)
                 + __logf(1.0f + __expf(-fabsf(v)));
            if (v > 0.0f && dist > 0) { pen += (unsigned)dist; cnt++; }
        }
    }

    // ---- Block reduction (deterministic tree) ----
    s_bce[tid] = bce; s_pen[tid] = pen; s_cnt[tid] = cnt;
    __syncthreads();
    for (int s = NTHREADS / 2; s > 0; s >>= 1) {
        if (tid < s) {
            s_bce[tid] += s_bce[tid + s];
            s_pen[tid] += s_pen[tid + s];
            s_cnt[tid] += s_cnt[tid + s];
        }
        __syncthreads();
    }

    const int nblk = gridDim.x * gridDim.y;
    if (tid == 0) {
        const int b = blockIdx.y * gridDim.x + blockIdx.x;
        g_bce[b] = s_bce[0];
        atomicAdd(&g_pen, (unsigned long long)s_pen[0]);
        atomicAdd(&g_cnt, (unsigned long long)s_cnt[0]);
        __threadfence();
        unsigned int ticket = atomicAdd(&g_done, 1u);
        s_last = (ticket == (unsigned)(nblk - 1));
    }
    __syncthreads();

    // ---- Last block finalizes (fixed-order sums -> deterministic) ----
    if (s_last) {
        __threadfence();
        float acc = 0.0f;
        for (int i = tid; i < nblk; i += NTHREADS) acc += g_bce[i];
        s_bce[tid] = acc;
        __syncthreads();
        for (int s = NTHREADS / 2; s > 0; s >>= 1) {
            if (tid < s) s_bce[tid] += s_bce[tid + s];
            __syncthreads();
        }
        if (tid == 0) {
            const double count = (double)gridDim.y * HDIM * WDIM;
            const double bce_mean = (double)s_bce[0] / count;
            const unsigned long long P = g_pen;
            const unsigned long long C = g_cnt;
            const double border = (P == 0) ? 0.0
                                : (double)P / (double)(C ? C : 1ull);
            out[0] = (float)(bce_mean + sqrt(border));
            g_pen = 0; g_cnt = 0; g_done = 0;   // restore state for next replay
        }
    }
}

extern "C" void kernel_launch(void* const* d_in, const int* in_sizes, int n_in,
                              void* d_out, int out_size) {
    const float* pred = (const float*)d_in[0];
    const float* targ = (const float*)d_in[1];
    const long long total = in_sizes[0];
    const int N = (int)(total / ((long long)HDIM * WDIM));   // 32

    dim3 grid(WDIM / CB, N);   // (8, 32) = 256 blocks
    dtl_main<<<grid, NTHREADS>>>(pred, targ, (float*)d_out);
}

// round 3
// speedup vs baseline: 2.0167x; 1.8242x over previous
#include <cuda_runtime.h>
#include <math.h>

// Shape fixed by dataset: (N=32, C=1, H=1024, W=1024) f32.
#define HDIM 1024
#define WDIM 1024
#define W4   (WDIM / 4)        // 256 float4 per row
#define C4   8                 // float4-columns per block
#define CB   (C4 * 4)          // 32 scalar columns per block
#define NWORDS (HDIM / 32)     // 32 words per column (one per thread row-group)
#define NTHREADS 256
#define MAXBLK 2048

__device__ unsigned long long g_pen;
__device__ unsigned long long g_cnt;
__device__ float              g_bce[MAXBLK];
__device__ unsigned int       g_done;

__global__ __launch_bounds__(NTHREADS)
void dtl_main(const float* __restrict__ pred, const float* __restrict__ targ,
              float* __restrict__ out) {
    __shared__ unsigned int mask[NWORDS][CB + 1];   // [word][col], stride 33
    __shared__ float        s_bce[NTHREADS];
    __shared__ unsigned int s_pen[NTHREADS];
    __shared__ unsigned int s_cnt[NTHREADS];
    __shared__ bool         s_last;

    const int tid = threadIdx.x;
    const int c   = tid & (C4 - 1);      // float4 column 0..7
    const int r   = tid >> 3;            // word index 0..31
    const int n   = blockIdx.y;
    const int cb  = c * 4;
    const int i0  = r * 32;

    const float4* t4 = (const float4*)(targ + (size_t)n * HDIM * WDIM)
                       + blockIdx.x * C4 + c;
    const float4* p4 = (const float4*)(pred + (size_t)n * HDIM * WDIM)
                       + blockIdx.x * C4 + c;

    // ---- Phase 1: build mask words via exact FFMA bit-packing ----
    {
        float lo0 = 0.f, lo1 = 0.f, lo2 = 0.f, lo3 = 0.f;
        float hi0 = 0.f, hi1 = 0.f, hi2 = 0.f, hi3 = 0.f;
        const float4* tp = t4 + (size_t)i0 * W4;
        #pragma unroll
        for (int b = 0; b < 16; ++b) {
            float4 t = __ldcs(tp); tp += W4;
            const float s = (float)(1u << b);
            lo0 += t.x * s; lo1 += t.y * s; lo2 += t.z * s; lo3 += t.w * s;
        }
        #pragma unroll
        for (int b = 0; b < 16; ++b) {
            float4 t = __ldcs(tp); tp += W4;
            const float s = (float)(1u << b);
            hi0 += t.x * s; hi1 += t.y * s; hi2 += t.z * s; hi3 += t.w * s;
        }
        mask[r][cb + 0] = (unsigned)lo0 | ((unsigned)hi0 << 16);
        mask[r][cb + 1] = (unsigned)lo1 | ((unsigned)hi1 << 16);
        mask[r][cb + 2] = (unsigned)lo2 | ((unsigned)hi2 << 16);
        mask[r][cb + 3] = (unsigned)lo3 | ((unsigned)hi3 << 16);
    }
    __syncthreads();

    // ---- Per-column boundary state from smem (once per thread) ----
    unsigned mw[4];
    int prev[4], next[4], nextAfter[4];
    #pragma unroll
    for (int j = 0; j < 4; ++j) {
        mw[j] = mask[r][cb + j];
        int p = -(1 << 20);
        for (int wd = r - 1; wd >= 0; --wd) {
            unsigned m = mask[wd][cb + j];
            if (m) { p = wd * 32 + 31 - __clz(m); break; }
        }
        prev[j] = p;
        int na = 1 << 20;
        for (int wd = r + 1; wd < NWORDS; ++wd) {
            unsigned m = mask[wd][cb + j];
            if (m) { na = wd * 32 + __ffs(m) - 1; break; }
        }
        nextAfter[j] = na;
        next[j] = mw[j] ? i0 + __ffs(mw[j]) - 1 : na;
    }

    // ---- Phase 2: stream predictions, accumulate ----
    float bce = 0.0f;
    unsigned int pen = 0, cnt = 0;
    {
        const float4* pp = p4 + (size_t)i0 * W4;
        #pragma unroll 8
        for (int b = 0; b < 32; ++b) {
            const int i = i0 + b;
            float4 p = __ldcs(pp); pp += W4;
            const float pv[4] = {p.x, p.y, p.z, p.w};
            #pragma unroll
            for (int j = 0; j < 4; ++j) {
                const unsigned bit = (mw[j] >> b) & 1u;
                if (bit) {
                    prev[j] = i;
                    const unsigned r2 = mw[j] & (0xFFFFFFFEu << b);
                    next[j] = r2 ? i0 + __ffs(r2) - 1 : nextAfter[j];
                }
                const int dist = min(min(i - prev[j], next[j] - i), HDIM);
                const float v = pv[j];
                bce += fmaxf(v, 0.0f) - (bit ? v : 0.0f)
                     + __logf(1.0f + __expf(-fabsf(v)));
                if (v > 0.0f && dist > 0) { pen += (unsigned)dist; cnt++; }
            }
        }
    }

    // ---- Block reduction (deterministic tree) ----
    s_bce[tid] = bce; s_pen[tid] = pen; s_cnt[tid] = cnt;
    __syncthreads();
    for (int s = NTHREADS / 2; s > 0; s >>= 1) {
        if (tid < s) {
            s_bce[tid] += s_bce[tid + s];
            s_pen[tid] += s_pen[tid + s];
            s_cnt[tid] += s_cnt[tid + s];
        }
        __syncthreads();
    }

    const int nblk = gridDim.x * gridDim.y;
    if (tid == 0) {
        const int blk = blockIdx.y * gridDim.x + blockIdx.x;
        g_bce[blk] = s_bce[0];
        atomicAdd(&g_pen, (unsigned long long)s_pen[0]);
        atomicAdd(&g_cnt, (unsigned long long)s_cnt[0]);
        __threadfence();
        unsigned int ticket = atomicAdd(&g_done, 1u);
        s_last = (ticket == (unsigned)(nblk - 1));
    }
    __syncthreads();

    // ---- Last block finalizes (fixed-order sums -> deterministic) ----
    if (s_last) {
        __threadfence();
        float acc = 0.0f;
        for (int i = tid; i < nblk; i += NTHREADS) acc += g_bce[i];
        s_bce[tid] = acc;
        __syncthreads();
        for (int s = NTHREADS / 2; s > 0; s >>= 1) {
            if (tid < s) s_bce[tid] += s_bce[tid + s];
            __syncthreads();
        }
        if (tid == 0) {
            const double count = (double)gridDim.y * HDIM * WDIM;
            const double bce_mean = (double)s_bce[0] / count;
            const unsigned long long P = g_pen;
            const unsigned long long C = g_cnt;
            const double border = (P == 0) ? 0.0
                                : (double)P / (double)(C ? C : 1ull);
            out[0] = (float)(bce_mean + sqrt(border));
            g_pen = 0; g_cnt = 0; g_done = 0;   // restore for next graph replay
        }
    }
}

extern "C" void kernel_launch(void* const* d_in, const int* in_sizes, int n_in,
                              void* d_out, int out_size) {
    const float* pred = (const float*)d_in[0];
    const float* targ = (const float*)d_in[1];
    const long long total = in_sizes[0];
    const int N = (int)(total / ((long long)HDIM * WDIM));   // 32

    dim3 grid(WDIM / CB, N);   // (32, 32) = 1024 blocks
    dtl_main<<<grid, NTHREADS>>>(pred, targ, (float*)d_out);
}